// round 6
// baseline (speedup 1.0000x reference)
#include <cuda_runtime.h>
#include <cuda_bf16.h>

// Problem constants (FullAttention_73650099192077)
#define B_SZ 4
#define L_Q  2048
#define S_K  2048
#define H_N  8
#define E_N  64
#define D_N  64

#define BM 64              // query rows per CTA (4 warps x 16)
#define BN 64              // keys per tile
#define NT 128
#define NTILES (S_K / BN)

#define TOT (B_SZ * H_N * 2048 * 64)   // elements per tensor

// Preprocessed split-bf16 tensors, layout [b*H+h][s][e] (rows of 64 bf16 = 128 B)
__device__ __nv_bfloat16 g_qh[TOT];
__device__ __nv_bfloat16 g_ql[TOT];
__device__ __nv_bfloat16 g_kh[TOT];
__device__ __nv_bfloat16 g_kl[TOT];
__device__ __nv_bfloat16 g_vh[TOT];
__device__ __nv_bfloat16 g_vl[TOT];

// ---- smem layout: double buffer x {KH, KL, VH, VL} of 64x64 bf16 (8 KB each) ----
#define SMB_KH 0
#define SMB_KL 8192
#define SMB_VH 16384
#define SMB_VL 24576
#define BUFSZ  32768
#define SM_TOTAL (2 * BUFSZ)

// =================== helpers ===================
static __device__ __forceinline__ unsigned smem_u32(const void* p) {
    unsigned a;
    asm("{ .reg .u64 t; cvta.to.shared.u64 t, %1; cvt.u32.u64 %0, t; }" : "=r"(a) : "l"(p));
    return a;
}
// row-swizzled byte address: row*128 + (bytecol XOR ((row&7)<<4))
static __device__ __forceinline__ unsigned swz(unsigned base, int row, int bytecol) {
    return base + (unsigned)(row * 128) + (unsigned)(bytecol ^ ((row & 7) << 4));
}
static __device__ __forceinline__ void ldsm_x4(unsigned* r, unsigned addr) {
    asm volatile("ldmatrix.sync.aligned.m8n8.x4.shared.b16 {%0,%1,%2,%3}, [%4];"
                 : "=r"(r[0]), "=r"(r[1]), "=r"(r[2]), "=r"(r[3]) : "r"(addr));
}
static __device__ __forceinline__ void ldsm_x4_t(unsigned* r, unsigned addr) {
    asm volatile("ldmatrix.sync.aligned.m8n8.x4.trans.shared.b16 {%0,%1,%2,%3}, [%4];"
                 : "=r"(r[0]), "=r"(r[1]), "=r"(r[2]), "=r"(r[3]) : "r"(addr));
}
static __device__ __forceinline__ void mma16816(float* c, const unsigned* a, unsigned b0, unsigned b1) {
    asm volatile("mma.sync.aligned.m16n8k16.row.col.f32.bf16.bf16.f32 "
                 "{%0,%1,%2,%3}, {%4,%5,%6,%7}, {%8,%9}, {%0,%1,%2,%3};"
                 : "+f"(c[0]), "+f"(c[1]), "+f"(c[2]), "+f"(c[3])
                 : "r"(a[0]), "r"(a[1]), "r"(a[2]), "r"(a[3]), "r"(b0), "r"(b1));
}
static __device__ __forceinline__ void split2(float x, float y, unsigned& h, unsigned& l) {
    __nv_bfloat162 hb = __floats2bfloat162_rn(x, y);
    float hx = __low2float(hb), hy = __high2float(hb);
    __nv_bfloat162 lb = __floats2bfloat162_rn(x - hx, y - hy);
    h = *reinterpret_cast<unsigned*>(&hb);
    l = *reinterpret_cast<unsigned*>(&lb);
}
static __device__ __forceinline__ void cpa16(unsigned saddr, const void* gp) {
    asm volatile("cp.async.cg.shared.global [%0], [%1], 16;" :: "r"(saddr), "l"(gp));
}
#define CP_COMMIT() asm volatile("cp.async.commit_group;" ::: "memory")
#define CP_WAIT(n)  asm volatile("cp.async.wait_group %0;" :: "n"(n) : "memory")

// =================== preprocess: fp32 [b,s,h,e] -> split bf16 [b*H+h][s][e] ===================
__global__ void prep_kernel(const float* __restrict__ src,
                            __nv_bfloat16* __restrict__ dh,
                            __nv_bfloat16* __restrict__ dl,
                            float scale)
{
    int idx = blockIdx.x * blockDim.x + threadIdx.x;      // one float4 per thread
    int e4 = idx & 15;
    int h  = (idx >> 4) & (H_N - 1);
    int s  = (idx >> 7) & 2047;
    int b  = idx >> 18;
    float4 v = *reinterpret_cast<const float4*>(src + (size_t)idx * 4);
    unsigned h0, l0, h1, l1;
    split2(v.x * scale, v.y * scale, h0, l0);
    split2(v.z * scale, v.w * scale, h1, l1);
    size_t doff = ((((size_t)b * H_N + h) * 2048 + s) * 64 + e4 * 4);
    *reinterpret_cast<uint2*>(dh + doff) = make_uint2(h0, h1);
    *reinterpret_cast<uint2*>(dl + doff) = make_uint2(l0, l1);
}

// =================== main kernel ===================
__global__ __launch_bounds__(NT, 2)
void fullattn_hmma2_kernel(float* __restrict__ O)
{
    extern __shared__ __align__(128) char smbuf[];
    const unsigned sb = smem_u32(smbuf);

    const int t    = threadIdx.x;
    const int wid  = t >> 5;
    const int lane = t & 31;
    const int g    = lane >> 2;
    const int tg   = lane & 3;
    const int l0   = blockIdx.x * BM;
    const int bh   = blockIdx.y;
    const int b    = bh >> 3;
    const int h    = bh & 7;

    const int row  = t >> 1;       // 0..63 (loader role)
    const int half = t & 1;        // 32-elem half of a row
    const size_t gbase = (size_t)bh * S_K * 64;

    // ---- Q tile (pre-scaled, pre-split) -> buf0 via cp.async, then ldmatrix to A-frags ----
    {
        const size_t qoff = ((size_t)bh * L_Q + l0 + row) * 64 + half * 32;
        #pragma unroll
        for (int c = 0; c < 4; c++) {
            const unsigned soff = half * 64 + c * 16;
            cpa16(swz(sb + SMB_KH, row, soff), g_qh + qoff + c * 8);
            cpa16(swz(sb + SMB_KL, row, soff), g_ql + qoff + c * 8);
        }
        CP_COMMIT();
        CP_WAIT(0);
        __syncthreads();
    }
    unsigned qh[16], ql[16];
    #pragma unroll
    for (int kb = 0; kb < 4; kb++) {
        const unsigned la = swz(sb, wid * 16 + (lane & 15), kb * 32 + (lane >> 4) * 16);
        ldsm_x4(&qh[kb * 4], la + SMB_KH);
        ldsm_x4(&ql[kb * 4], la + SMB_KL);
    }
    __syncthreads();

    // ---- K/V tile loader (cp.async into swizzled smem) ----
    auto load_tile = [&](int tile, int bufsel) {
        const unsigned bb = sb + bufsel * BUFSZ;
        const size_t off = gbase + ((size_t)(tile * BN + row)) * 64 + half * 32;
        #pragma unroll
        for (int c = 0; c < 4; c++) {
            const unsigned soff = half * 64 + c * 16;
            cpa16(swz(bb + SMB_KH, row, soff), g_kh + off + c * 8);
            cpa16(swz(bb + SMB_KL, row, soff), g_kl + off + c * 8);
            cpa16(swz(bb + SMB_VH, row, soff), g_vh + off + c * 8);
            cpa16(swz(bb + SMB_VL, row, soff), g_vl + off + c * 8);
        }
        CP_COMMIT();
    };

    load_tile(0, 0);
    load_tile(1, 1);

    float o[8][4];
    #pragma unroll
    for (int j = 0; j < 8; j++)
        #pragma unroll
        for (int i = 0; i < 4; i++) o[j][i] = 0.0f;
    float m0 = -1e30f, m1 = -1e30f;
    float l0s = 0.0f, l1s = 0.0f;

    for (int tile = 0; tile < NTILES; tile++) {
        const unsigned bb = sb + (tile & 1) * BUFSZ;

        CP_WAIT(1);            // current tile's group complete (one stays in flight)
        __syncthreads();

        // ---- QK^T (3-MMA split) ----
        float sacc[8][4];
        #pragma unroll
        for (int j = 0; j < 8; j++)
            #pragma unroll
            for (int i = 0; i < 4; i++) sacc[j][i] = 0.0f;

        #pragma unroll
        for (int jj = 0; jj < 4; jj++) {
            #pragma unroll
            for (int kb = 0; kb < 4; kb++) {
                const unsigned la = swz(bb, 16 * jj + (lane & 15), kb * 32 + (lane >> 4) * 16);
                unsigned bh4[4], bl4[4];
                ldsm_x4(bh4, la + SMB_KH);
                ldsm_x4(bl4, la + SMB_KL);
                mma16816(sacc[2 * jj],     &qh[kb * 4], bh4[0], bh4[2]);
                mma16816(sacc[2 * jj],     &qh[kb * 4], bl4[0], bl4[2]);
                mma16816(sacc[2 * jj],     &ql[kb * 4], bh4[0], bh4[2]);
                mma16816(sacc[2 * jj + 1], &qh[kb * 4], bh4[1], bh4[3]);
                mma16816(sacc[2 * jj + 1], &qh[kb * 4], bl4[1], bl4[3]);
                mma16816(sacc[2 * jj + 1], &ql[kb * 4], bh4[1], bh4[3]);
            }
        }

        // ---- online softmax (rows g, g+8; quad reduction) ----
        float mx0 = -1e30f, mx1 = -1e30f;
        #pragma unroll
        for (int j = 0; j < 8; j++) {
            mx0 = fmaxf(mx0, fmaxf(sacc[j][0], sacc[j][1]));
            mx1 = fmaxf(mx1, fmaxf(sacc[j][2], sacc[j][3]));
        }
        #pragma unroll
        for (int off = 1; off < 4; off <<= 1) {
            mx0 = fmaxf(mx0, __shfl_xor_sync(0xffffffffu, mx0, off));
            mx1 = fmaxf(mx1, __shfl_xor_sync(0xffffffffu, mx1, off));
        }
        const float nm0 = fmaxf(m0, mx0), nm1 = fmaxf(m1, mx1);
        const float a0 = __expf(m0 - nm0), a1 = __expf(m1 - nm1);
        m0 = nm0; m1 = nm1;

        float rs0 = 0.0f, rs1 = 0.0f;
        #pragma unroll
        for (int j = 0; j < 8; j++) {
            sacc[j][0] = __expf(sacc[j][0] - nm0);
            sacc[j][1] = __expf(sacc[j][1] - nm0);
            sacc[j][2] = __expf(sacc[j][2] - nm1);
            sacc[j][3] = __expf(sacc[j][3] - nm1);
            rs0 += sacc[j][0] + sacc[j][1];
            rs1 += sacc[j][2] + sacc[j][3];
        }
        #pragma unroll
        for (int off = 1; off < 4; off <<= 1) {
            rs0 += __shfl_xor_sync(0xffffffffu, rs0, off);
            rs1 += __shfl_xor_sync(0xffffffffu, rs1, off);
        }
        l0s = l0s * a0 + rs0;
        l1s = l1s * a1 + rs1;
        #pragma unroll
        for (int j = 0; j < 8; j++) {
            o[j][0] *= a0; o[j][1] *= a0;
            o[j][2] *= a1; o[j][3] *= a1;
        }

        // ---- pack P (C-frag -> A-frag identity), split hi/lo ----
        unsigned ph[16], pl[16];
        #pragma unroll
        for (int kb = 0; kb < 4; kb++) {
            split2(sacc[2 * kb][0],     sacc[2 * kb][1],     ph[kb * 4 + 0], pl[kb * 4 + 0]);
            split2(sacc[2 * kb][2],     sacc[2 * kb][3],     ph[kb * 4 + 1], pl[kb * 4 + 1]);
            split2(sacc[2 * kb + 1][0], sacc[2 * kb + 1][1], ph[kb * 4 + 2], pl[kb * 4 + 2]);
            split2(sacc[2 * kb + 1][2], sacc[2 * kb + 1][3], ph[kb * 4 + 3], pl[kb * 4 + 3]);
        }

        // ---- PV (3-MMA split; V via ldmatrix.trans) ----
        #pragma unroll
        for (int jj = 0; jj < 4; jj++) {
            #pragma unroll
            for (int kb = 0; kb < 4; kb++) {
                const unsigned la = swz(bb, 16 * kb + (lane & 15), jj * 32 + (lane >> 4) * 16);
                unsigned vh4[4], vl4[4];
                ldsm_x4_t(vh4, la + SMB_VH);
                ldsm_x4_t(vl4, la + SMB_VL);
                mma16816(o[2 * jj],     &ph[kb * 4], vh4[0], vh4[1]);
                mma16816(o[2 * jj],     &ph[kb * 4], vl4[0], vl4[1]);
                mma16816(o[2 * jj],     &pl[kb * 4], vh4[0], vh4[1]);
                mma16816(o[2 * jj + 1], &ph[kb * 4], vh4[2], vh4[3]);
                mma16816(o[2 * jj + 1], &ph[kb * 4], vl4[2], vl4[3]);
                mma16816(o[2 * jj + 1], &pl[kb * 4], vh4[2], vh4[3]);
            }
        }

        __syncthreads();       // all warps done with buf[tile&1]
        if (tile + 2 < NTILES) load_tile(tile + 2, tile & 1);
        else                   CP_COMMIT();   // keep wait_group bookkeeping aligned
    }

    // ---- epilogue: normalize + store ----
    const float inv0 = 1.0f / l0s;
    const float inv1 = 1.0f / l1s;
    const int r0 = l0 + wid * 16 + g;
    float* ob0 = O + ((size_t)(b * L_Q + r0)     * H_N + h) * D_N;
    float* ob1 = O + ((size_t)(b * L_Q + r0 + 8) * H_N + h) * D_N;
    #pragma unroll
    for (int j = 0; j < 8; j++) {
        const int d = j * 8 + tg * 2;
        *reinterpret_cast<float2*>(ob0 + d) = make_float2(o[j][0] * inv0, o[j][1] * inv0);
        *reinterpret_cast<float2*>(ob1 + d) = make_float2(o[j][2] * inv1, o[j][3] * inv1);
    }
}

extern "C" void kernel_launch(void* const* d_in, const int* in_sizes, int n_in,
                              void* d_out, int out_size)
{
    const float* Q = (const float*)d_in[0];
    const float* K = (const float*)d_in[1];
    const float* V = (const float*)d_in[2];
    float* O = (float*)d_out;
    (void)in_sizes; (void)n_in; (void)out_size;

    void *qh, *ql, *kh, *kl, *vh, *vl;
    cudaGetSymbolAddress(&qh, g_qh);
    cudaGetSymbolAddress(&ql, g_ql);
    cudaGetSymbolAddress(&kh, g_kh);
    cudaGetSymbolAddress(&kl, g_kl);
    cudaGetSymbolAddress(&vh, g_vh);
    cudaGetSymbolAddress(&vl, g_vl);

    const int pblocks = (TOT / 4) / 256;
    prep_kernel<<<pblocks, 256>>>(Q, (__nv_bfloat16*)qh, (__nv_bfloat16*)ql, 0.125f);
    prep_kernel<<<pblocks, 256>>>(K, (__nv_bfloat16*)kh, (__nv_bfloat16*)kl, 1.0f);
    prep_kernel<<<pblocks, 256>>>(V, (__nv_bfloat16*)vh, (__nv_bfloat16*)vl, 1.0f);

    cudaFuncSetAttribute(fullattn_hmma2_kernel,
                         cudaFuncAttributeMaxDynamicSharedMemorySize, SM_TOTAL);

    dim3 grid(L_Q / BM, B_SZ * H_N);    // 32 x 32 = 1024 CTAs
    fullattn_hmma2_kernel<<<grid, NT, SM_TOTAL>>>(O);
}